// round 17
// baseline (speedup 1.0000x reference)
#include <cuda_runtime.h>

typedef unsigned long long u64;

#define BLK   256
#define TROWS 256     // rows per block; thread t handles rows r and r+128 (packed)
#define XSTRF 260     // float stride per feature in x tile (= 130 float2)

// dup'd weight tables (each value stored twice: (w,w) pairs), float offsets
#define D_S0 0        // 136*32  sym w0   (scaled a2)
#define D_S2 4352     // 136*32  sym w2   (scaled a2/sqrt3)
#define D_S4 8704     // 136*32  sym w4   (scaled a1; m-scales at epilogue)
#define D_A3 13056    // 120*32  antisym w3 (scaled a1/sqrt2)
#define D_W1 16896    // 4096*2  w1       (scaled a1)
#define W2_TOTAL 25088
#define SMEM_FLOATS (W2_TOTAL + 64 * XSTRF)
#define SMEM_BYTES  (SMEM_FLOATS * 4)

#define A1F    0.0625f
#define A2F    0.04419417382415922f
#define A2_3F  0.02551551815399144f
#define A1S2F  0.04419417382415922f
#define S2F    0.7071067811865476f
#define IS6F   0.4082482904638630f

__device__ float g_ws[W2_TOTAL];

__global__ void prep_kernel(const float* __restrict__ w0, const float* __restrict__ w1,
                            const float* __restrict__ w2, const float* __restrict__ w3,
                            const float* __restrict__ w4)
{
    int idx = blockIdx.x * blockDim.x + threadIdx.x;   // (u,v,w) flattened, 4096
    if (idx >= 4096) return;
    int w = idx & 15;
    int v = (idx >> 4) & 15;
    int u = idx >> 8;
    int sidx = ((v * 16 + u) << 4) + w;

    float w1v = A1F * w1[idx];
    g_ws[D_W1 + 2 * idx]     = w1v;
    g_ws[D_W1 + 2 * idx + 1] = w1v;

    if (u <= v) {
        int p = u * 16 - (u * (u - 1)) / 2 + (v - u);
        float f0 = (u == v) ? w0[idx] : (w0[idx] + w0[sidx]);
        float f2 = (u == v) ? w2[idx] : (w2[idx] + w2[sidx]);
        float f4 = (u == v) ? w4[idx] : (w4[idx] + w4[sidx]);
        float v0 = A2F * f0, v2 = A2_3F * f2, v4 = A1F * f4;
        g_ws[D_S0 + p * 32 + 2 * w] = v0; g_ws[D_S0 + p * 32 + 2 * w + 1] = v0;
        g_ws[D_S2 + p * 32 + 2 * w] = v2; g_ws[D_S2 + p * 32 + 2 * w + 1] = v2;
        g_ws[D_S4 + p * 32 + 2 * w] = v4; g_ws[D_S4 + p * 32 + 2 * w + 1] = v4;
    }
    if (u < v) {
        int pa = 15 * u - (u * (u - 1)) / 2 + (v - u - 1);
        float v3 = A1S2F * (w3[idx] - w3[sidx]);
        g_ws[D_A3 + pa * 32 + 2 * w] = v3; g_ws[D_A3 + pa * 32 + 2 * w + 1] = v3;
    }
}

// ---- packed fp32 helpers -------------------------------------------------
__device__ __forceinline__ u64 dup2(float s)
{
    unsigned int b = __float_as_uint(s);
    u64 r;
    asm("mov.b64 %0, {%1, %1};" : "=l"(r) : "r"(b));
    return r;
}
__device__ __forceinline__ void fma2(u64& d, u64 a, u64 b)
{
    asm("fma.rn.f32x2 %0, %1, %2, %0;" : "+l"(d) : "l"(a), "l"(b));
}
__device__ __forceinline__ u64 fma2n(u64 a, u64 b, u64 c)
{
    u64 d;
    asm("fma.rn.f32x2 %0, %1, %2, %3;" : "=l"(d) : "l"(a), "l"(b), "l"(c));
    return d;
}
__device__ __forceinline__ u64 mul2(u64 a, u64 b)
{
    u64 d;
    asm("mul.rn.f32x2 %0, %1, %2;" : "=l"(d) : "l"(a), "l"(b));
    return d;
}
__device__ __forceinline__ u64 add2(u64 a, u64 b)
{
    u64 d;
    asm("add.rn.f32x2 %0, %1, %2;" : "=l"(d) : "l"(a), "l"(b));
    return d;
}
__device__ __forceinline__ void unpk(u64 v, float& lo, float& hi)
{
    unsigned int l, h;
    asm("mov.b64 {%0, %1}, %2;" : "=r"(l), "=r"(h) : "l"(v));
    lo = __uint_as_float(l);
    hi = __uint_as_float(h);
}

// ---- row-packed axpy over one dup'd 32-float weight row ------------------
// acc[m*16 + w] += f[m] * (w_w, w_w); f[m] = (qA, qB) packed per-row features.
template<int M>
__device__ __forceinline__ void axpyRP(u64* acc, const float* wb, const u64* f)
{
    const ulonglong2* wr = reinterpret_cast<const ulonglong2*>(wb);
    u64 wd[16];
#pragma unroll
    for (int q = 0; q < 8; q++) {
        ulonglong2 wv = wr[q];
        wd[2 * q] = wv.x; wd[2 * q + 1] = wv.y;
    }
#pragma unroll
    for (int w = 0; w < 16; w++)
#pragma unroll
        for (int m = 0; m < M; m++)
            fma2(acc[m * 16 + w], f[m], wd[w]);
}

// ---------------------------------------------------------------------------
// Row-packed main kernel. 2 roles x 128 threads; thread = rows (r, r+128).
//   role 0 (warps 0-3): o_2e + o_1o[w 0..7]
//   role 1 (warps 4-7): o_0e + o_1e + o_1o[w 8..15]
// All accumulators pack (rowA, rowB); features load as LDS.64 pairs; weight
// tables are pre-duplicated so no dup movs exist anywhere in the hot loops.
// ---------------------------------------------------------------------------
__global__ __launch_bounds__(BLK, 1)
void tsq_kernel(const float* __restrict__ x, float* __restrict__ out, int n)
{
    extern __shared__ float smem[];
    float* ws = smem;                       // dup'd weights, W2_TOTAL floats
    float* xs = smem + W2_TOTAL;            // x tile: feat-major float2 (rowA,rowB)
    int tid = threadIdx.x;

    {
        const float4* gw = reinterpret_cast<const float4*>(g_ws);
        float4* sw = reinterpret_cast<float4*>(ws);
        for (int i = tid; i < W2_TOTAL / 4; i += BLK) sw[i] = gw[i];
    }
    int row0 = blockIdx.x * TROWS;
    {
        const float4* x4 = reinterpret_cast<const float4*>(x);
#pragma unroll
        for (int i = 0; i < 16; i++) {
            int lin = i * BLK + tid;        // 4096 = 256 rows * 16 float4
            int rr = lin >> 4, c = lin & 15;
            int r = rr & 127, hi = rr >> 7;
            float4 val = make_float4(0.f, 0.f, 0.f, 0.f);
            if (row0 + rr < n) val = x4[(size_t)(row0 + rr) * 16 + c];
            xs[(4 * c + 0) * XSTRF + 2 * r + hi] = val.x;
            xs[(4 * c + 1) * XSTRF + 2 * r + hi] = val.y;
            xs[(4 * c + 2) * XSTRF + 2 * r + hi] = val.z;
            xs[(4 * c + 3) * XSTRF + 2 * r + hi] = val.w;
        }
    }
    __syncthreads();

    int role = tid >> 7;
    int r    = tid & 127;
    int zA = row0 + r;
    if (zA >= n) return;
    int zB = zA + 128;
    bool vB = (zB < n);
    float* oA = out + (size_t)zA * 192;
    float* oB = out + (size_t)zB * 192;
    const u64* xu = reinterpret_cast<const u64*>(xs) + r;   // xu[f*130] = feature f

    const u64 NEG1 = dup2(-1.0f);

    if (role == 0) {
        // ===== o_2e: acc[m*16+w] packs (rowA, rowB)
        u64 acc[80];
#pragma unroll
        for (int k = 0; k < 80; k++) acc[k] = 0ULL;
        const float* s4r = ws + D_S4;

        for (int u = 0; u < 16; u++) {
            u64 ax2 = xu[(16 + 3 * u + 0) * 130];
            u64 ay2 = xu[(16 + 3 * u + 1) * 130];
            u64 az2 = xu[(16 + 3 * u + 2) * 130];
            {   // diagonal
                u64 q[5];
                u64 pxx = mul2(ax2, ax2), pyy = mul2(ay2, ay2), pzz = mul2(az2, az2);
                u64 t0 = mul2(ax2, ay2); q[0] = add2(t0, t0);
                u64 t1 = mul2(ay2, az2); q[1] = add2(t1, t1);
                q[2] = fma2n(add2(pxx, pyy), NEG1, add2(pzz, pzz));
                u64 t3 = mul2(ax2, az2); q[3] = add2(t3, t3);
                q[4] = fma2n(pyy, NEG1, pxx);
                axpyRP<5>(acc, s4r, q); s4r += 32;
            }
            for (int v = u + 1; v < 16; v++) {
                u64 bx2 = xu[(16 + 3 * v + 0) * 130];
                u64 by2 = xu[(16 + 3 * v + 1) * 130];
                u64 bz2 = xu[(16 + 3 * v + 2) * 130];
                u64 q[5];
                u64 pxx = mul2(ax2, bx2), pyy = mul2(ay2, by2), pzz = mul2(az2, bz2);
                q[0] = fma2n(ax2, by2, mul2(ay2, bx2));
                q[1] = fma2n(ay2, bz2, mul2(az2, by2));
                q[2] = fma2n(add2(pxx, pyy), NEG1, add2(pzz, pzz));
                q[3] = fma2n(ax2, bz2, mul2(az2, bx2));
                q[4] = fma2n(pyy, NEG1, pxx);
                axpyRP<5>(acc, s4r, q); s4r += 32;
            }
        }
        const float csc[5] = {S2F, S2F, IS6F, S2F, S2F};
#pragma unroll
        for (int m = 0; m < 5; m++)
#pragma unroll
            for (int w = 0; w < 16; w++) {
                float lo, hi; unpk(acc[m * 16 + w], lo, hi);
                oA[112 + 5 * w + m] = lo * csc[m];
                if (vB) oB[112 + 5 * w + m] = hi * csc[m];
            }
    } else {
        // ===== o_0e (paths 0+2) + o_1e (path 3)
        u64 c0[16], e1[48];
#pragma unroll
        for (int k = 0; k < 16; k++) c0[k] = 0ULL;
#pragma unroll
        for (int k = 0; k < 48; k++) e1[k] = 0ULL;
        const float* s0r = ws + D_S0;
        const float* s2r = ws + D_S2;
        const float* a3r = ws + D_A3;

        for (int u = 0; u < 16; u++) {
            u64 a02 = xu[u * 130];
            u64 ax2 = xu[(16 + 3 * u + 0) * 130];
            u64 ay2 = xu[(16 + 3 * u + 1) * 130];
            u64 az2 = xu[(16 + 3 * u + 2) * 130];
            {   // diagonal: cross vanishes
                u64 f[1];
                f[0] = mul2(a02, a02);
                axpyRP<1>(c0, s0r, f); s0r += 32;
                f[0] = fma2n(ax2, ax2, fma2n(ay2, ay2, mul2(az2, az2)));
                axpyRP<1>(c0, s2r, f); s2r += 32;
            }
            for (int v = u + 1; v < 16; v++) {
                u64 b02 = xu[v * 130];
                u64 bx2 = xu[(16 + 3 * v + 0) * 130];
                u64 by2 = xu[(16 + 3 * v + 1) * 130];
                u64 bz2 = xu[(16 + 3 * v + 2) * 130];
                u64 f[1];
                f[0] = mul2(a02, b02);
                axpyRP<1>(c0, s0r, f); s0r += 32;
                f[0] = fma2n(ax2, bx2, fma2n(ay2, by2, mul2(az2, bz2)));
                axpyRP<1>(c0, s2r, f); s2r += 32;
                u64 c[3];
                c[0] = fma2n(mul2(az2, by2), NEG1, mul2(ay2, bz2));   // cx
                c[1] = fma2n(mul2(ax2, bz2), NEG1, mul2(az2, bx2));   // cy
                c[2] = fma2n(mul2(ay2, bx2), NEG1, mul2(ax2, by2));   // cz
                axpyRP<3>(e1, a3r, c); a3r += 32;
            }
        }
        {   // o_0e
            float loA[16], hiB[16];
#pragma unroll
            for (int w = 0; w < 16; w++) unpk(c0[w], loA[w], hiB[w]);
            float4* o4 = reinterpret_cast<float4*>(oA);
#pragma unroll
            for (int j = 0; j < 4; j++)
                o4[j] = make_float4(loA[4 * j], loA[4 * j + 1], loA[4 * j + 2], loA[4 * j + 3]);
            if (vB) {
                float4* p4 = reinterpret_cast<float4*>(oB);
#pragma unroll
                for (int j = 0; j < 4; j++)
                    p4[j] = make_float4(hiB[4 * j], hiB[4 * j + 1], hiB[4 * j + 2], hiB[4 * j + 3]);
            }
        }
#pragma unroll
        for (int m = 0; m < 3; m++)
#pragma unroll
            for (int w = 0; w < 16; w++) {
                float lo, hi; unpk(e1[m * 16 + w], lo, hi);
                oA[64 + 3 * w + m] = lo;
                if (vB) oB[64 + 3 * w + m] = hi;
            }
    }

    // ===== path 1 (0e x 1o -> 1o), factorized; role handles 8 of 16 w.
    //   T_w = sum_u a0_u * w1_w  (row-packed, a0 loaded packed: no dups)
    {
        u64 a02[16];
#pragma unroll
        for (int u = 0; u < 16; u++) a02[u] = xu[u * 130];

        u64 p[24];
#pragma unroll
        for (int k = 0; k < 24; k++) p[k] = 0ULL;

        const float* w1b = ws + D_W1 + role * 16;

        for (int v = 0; v < 16; v++) {
            u64 bx2 = xu[(16 + 3 * v + 0) * 130];
            u64 by2 = xu[(16 + 3 * v + 1) * 130];
            u64 bz2 = xu[(16 + 3 * v + 2) * 130];

            u64 T[8];
            {
                const ulonglong2* wr = reinterpret_cast<const ulonglong2*>(w1b + v * 32);
#pragma unroll
                for (int q = 0; q < 4; q++) {
                    ulonglong2 wv = wr[q];
                    T[2 * q] = mul2(a02[0], wv.x);
                    T[2 * q + 1] = mul2(a02[0], wv.y);
                }
            }
#pragma unroll
            for (int u = 1; u < 16; u++) {
                const ulonglong2* wr =
                    reinterpret_cast<const ulonglong2*>(w1b + u * 512 + v * 32);
#pragma unroll
                for (int q = 0; q < 4; q++) {
                    ulonglong2 wv = wr[q];
                    fma2(T[2 * q], a02[u], wv.x);
                    fma2(T[2 * q + 1], a02[u], wv.y);
                }
            }
#pragma unroll
            for (int h = 0; h < 8; h++) {
                fma2(p[h],      T[h], bx2);
                fma2(p[8 + h],  T[h], by2);
                fma2(p[16 + h], T[h], bz2);
            }
        }
#pragma unroll
        for (int m = 0; m < 3; m++)
#pragma unroll
            for (int h = 0; h < 8; h++) {
                float lo, hi; unpk(p[m * 8 + h], lo, hi);
                int w = role * 8 + h;
                oA[16 + 3 * w + m] = lo;
                if (vB) oB[16 + 3 * w + m] = hi;
            }
    }
}

// ---------------------------------------------------------------------------
extern "C" void kernel_launch(void* const* d_in, const int* in_sizes, int n_in,
                              void* d_out, int out_size)
{
    const float* x  = (const float*)d_in[0];
    const float* w0 = (const float*)d_in[1];
    const float* w1 = (const float*)d_in[2];
    const float* w2 = (const float*)d_in[3];
    const float* w3 = (const float*)d_in[4];
    const float* w4 = (const float*)d_in[5];
    float* out = (float*)d_out;
    int n = in_sizes[0] / 64;

    cudaFuncSetAttribute(tsq_kernel, cudaFuncAttributeMaxDynamicSharedMemorySize, SMEM_BYTES);

    prep_kernel<<<16, 256>>>(w0, w1, w2, w3, w4);
    tsq_kernel<<<(n + TROWS - 1) / TROWS, BLK, SMEM_BYTES>>>(x, out, n);
}